// round 9
// baseline (speedup 1.0000x reference)
#include <cuda_runtime.h>

#define NCTA 128
#define NTHR 512
#define TSTEPS 512
#define Bb 64
#define Hh 1024
#define K2H 2048

typedef unsigned long long u64_t;

// Persistent device state. All transposed: [col][row], row=batch.
__device__ float g_sT[9][Hh * Bb];
__device__ float g_hT[Hh * Bb];
__device__ float g_embT[Hh * Bb];
__device__ unsigned g_count = 0;   // monotonic across barriers AND graph replays
__device__ unsigned g_gen = 0;

union F4U { float4 f; u64_t u[2]; };

// ---- packed f32x2 (Blackwell) ----
__device__ __forceinline__ u64_t pack2(float lo, float hi) {
    u64_t r; asm("mov.b64 %0, {%1, %2};" : "=l"(r) : "f"(lo), "f"(hi)); return r;
}
__device__ __forceinline__ void fma2(u64_t& d, u64_t a, u64_t b) {
    asm("fma.rn.f32x2 %0, %1, %2, %3;" : "=l"(d) : "l"(a), "l"(b), "l"(d));
}
__device__ __forceinline__ u64_t add2(u64_t a, u64_t b) {
    u64_t d; asm("add.rn.f32x2 %0, %1, %2;" : "=l"(d) : "l"(a), "l"(b)); return d;
}
__device__ __forceinline__ float ldcg_f(const float* p) {
    float v; asm volatile("ld.global.cg.f32 %0, [%1];" : "=f"(v) : "l"(p)); return v;
}
__device__ __forceinline__ float4 ldcg_f4(const float* p) {
    float4 v;
    asm volatile("ld.global.cg.v4.f32 {%0,%1,%2,%3}, [%4];"
                 : "=f"(v.x), "=f"(v.y), "=f"(v.z), "=f"(v.w) : "l"(p));
    return v;
}

__device__ __forceinline__ float sigm(float x) { return 1.f / (1.f + expf(-x)); }
__device__ __forceinline__ float actf(int code, float x) {
    switch (code) {
        case 0:  return tanhf(x);
        case 1:  return fmaxf(x, 0.f);
        case 2:  return sigm(x);
        default: return x;
    }
}

// Monotonic-generation grid barrier (proven fastest variant).
__device__ __forceinline__ void grid_sync() {
    __syncthreads();
    if (threadIdx.x == 0) {
        __threadfence();
        unsigned arr = atomicAdd(&g_count, 1u) + 1u;
        unsigned want = (arr + NCTA - 1u) / NCTA;
        if (arr % NCTA == 0u) atomicAdd(&g_gen, 1u);
        while (*((volatile unsigned*)&g_gen) < want) { }
        __threadfence();
    }
    __syncthreads();
}

// One 8-col x 64-row output tile: out = gated(Sin); pre-act = x @ W (W:[K][2048], c|h halves).
// x transposed [k][64]; 16 warps split K. Distance-4 register pipeline: 12 LDGs in
// flight per warp, consumption 4 k behind issue.
__device__ __noinline__ void gemm_tile(
    const float* __restrict__ W, const float* __restrict__ xA,
    const float* __restrict__ xB, int Ka, int K,
    const float* __restrict__ gateT, float* __restrict__ outT,
    int j0, int act, u64_t* red)
{
    const int lane = threadIdx.x & 31;
    const int warp = threadIdx.x >> 5;
    const int ct = lane & 1;           // 2 col-threads: 4 cols each
    const int g  = lane >> 1;          // 16 row-groups: 4 rows each
    const int colbase = j0 + ct * 4;
    const int rowbase = g * 4;
    const int kslice = K >> 4;         // 16-way K split
    const int kbeg = warp * kslice;

    const float* xp = ((kbeg < Ka) ? (xA + (size_t)kbeg * Bb)
                                   : (xB + (size_t)(kbeg - Ka) * Bb)) + rowbase;
    const float* wp = W + (size_t)kbeg * K2H + colbase;

    u64_t acc[4][2][2];                // [row r][colpair cp][half h]
    #pragma unroll
    for (int r = 0; r < 4; r++)
        #pragma unroll
        for (int cp = 0; cp < 2; cp++) { acc[r][cp][0] = 0ull; acc[r][cp][1] = 0ull; }

    // distance-4 pipeline buffers
    float4 xq[4];
    F4U wcq[4], whq[4];
    #pragma unroll
    for (int p = 0; p < 4; p++) {
        xq[p]    = ldcg_f4(xp + (size_t)p * Bb);
        wcq[p].f = __ldg((const float4*)(wp + (size_t)p * K2H));
        whq[p].f = __ldg((const float4*)(wp + (size_t)p * K2H + Hh));
    }

    #pragma unroll 4
    for (int k = 0; k < kslice - 4; k++) {
        const int b = k & 3;
        float4 xv = xq[b];
        F4U wc = wcq[b], wh = whq[b];
        // prefetch k+4 into the freed slot
        xq[b]    = ldcg_f4(xp + (size_t)(k + 4) * Bb);
        wcq[b].f = __ldg((const float4*)(wp + (size_t)(k + 4) * K2H));
        whq[b].f = __ldg((const float4*)(wp + (size_t)(k + 4) * K2H + Hh));

        u64_t xb;
        xb = pack2(xv.x, xv.x);
        fma2(acc[0][0][0], xb, wc.u[0]); fma2(acc[0][1][0], xb, wc.u[1]);
        fma2(acc[0][0][1], xb, wh.u[0]); fma2(acc[0][1][1], xb, wh.u[1]);
        xb = pack2(xv.y, xv.y);
        fma2(acc[1][0][0], xb, wc.u[0]); fma2(acc[1][1][0], xb, wc.u[1]);
        fma2(acc[1][0][1], xb, wh.u[0]); fma2(acc[1][1][1], xb, wh.u[1]);
        xb = pack2(xv.z, xv.z);
        fma2(acc[2][0][0], xb, wc.u[0]); fma2(acc[2][1][0], xb, wc.u[1]);
        fma2(acc[2][0][1], xb, wh.u[0]); fma2(acc[2][1][1], xb, wh.u[1]);
        xb = pack2(xv.w, xv.w);
        fma2(acc[3][0][0], xb, wc.u[0]); fma2(acc[3][1][0], xb, wc.u[1]);
        fma2(acc[3][0][1], xb, wh.u[0]); fma2(acc[3][1][1], xb, wh.u[1]);
    }

    // epilogue: last 4 k from buffers
    #pragma unroll
    for (int p = 0; p < 4; p++) {
        const int b = (kslice - 4 + p) & 3;
        float4 xv = xq[b];
        F4U wc = wcq[b], wh = whq[b];
        u64_t xb;
        xb = pack2(xv.x, xv.x);
        fma2(acc[0][0][0], xb, wc.u[0]); fma2(acc[0][1][0], xb, wc.u[1]);
        fma2(acc[0][0][1], xb, wh.u[0]); fma2(acc[0][1][1], xb, wh.u[1]);
        xb = pack2(xv.y, xv.y);
        fma2(acc[1][0][0], xb, wc.u[0]); fma2(acc[1][1][0], xb, wc.u[1]);
        fma2(acc[1][0][1], xb, wh.u[0]); fma2(acc[1][1][1], xb, wh.u[1]);
        xb = pack2(xv.z, xv.z);
        fma2(acc[2][0][0], xb, wc.u[0]); fma2(acc[2][1][0], xb, wc.u[1]);
        fma2(acc[2][0][1], xb, wh.u[0]); fma2(acc[2][1][1], xb, wh.u[1]);
        xb = pack2(xv.w, xv.w);
        fma2(acc[3][0][0], xb, wc.u[0]); fma2(acc[3][1][0], xb, wc.u[1]);
        fma2(acc[3][0][1], xb, wh.u[0]); fma2(acc[3][1][1], xb, wh.u[1]);
    }

    // Stage 1: warps 8..15 store partials into slot (warp-8).
    if (warp >= 8) {
        u64_t* my = red + ((size_t)((warp - 8) * 32 + lane)) * 16;
        #pragma unroll
        for (int r = 0; r < 4; r++)
            #pragma unroll
            for (int cp = 0; cp < 2; cp++) {
                my[(r * 4 + cp * 2) + 0] = acc[r][cp][0];
                my[(r * 4 + cp * 2) + 1] = acc[r][cp][1];
            }
    }
    __syncthreads();

    // Stage 2: warps 0..7 add partner partials into slot warp.
    if (warp < 8) {
        u64_t* my = red + ((size_t)(warp * 32 + lane)) * 16;
        #pragma unroll
        for (int r = 0; r < 4; r++)
            #pragma unroll
            for (int cp = 0; cp < 2; cp++) {
                int i0 = r * 4 + cp * 2;
                my[i0 + 0] = add2(my[i0 + 0], acc[r][cp][0]);
                my[i0 + 1] = add2(my[i0 + 1], acc[r][cp][1]);
            }
    }
    __syncthreads();

    // Stage 3: 512 threads finalize 512 outputs (8 cols x 64 rows).
    {
        const int t   = threadIdx.x;
        const int c8  = t & 7;
        const int row = t >> 3;
        const int sct = c8 >> 2;
        const int cp  = (c8 >> 1) & 1;
        const int par = c8 & 1;
        const int sg  = row >> 2;
        const int r   = row & 3;
        const int slane = sg * 2 + sct;
        const float* redf = (const float*)red;
        const int fbase = slane * 32 + (r * 4 + cp * 2) * 2 + par;

        float sc = 0.f, sh = 0.f;
        #pragma unroll
        for (int s = 0; s < 8; s++) {
            const float* rp = redf + (size_t)s * 32 * 32 + fbase;
            sc += rp[0];
            sh += rp[2];
        }
        const int col = j0 + c8;
        const size_t o = (size_t)col * Bb + row;
        float sp = ldcg_f(gateT + o);
        float cv = sigm(sc);
        float hv = actf(act, sh);
        outT[o] = sp + cv * (hv - sp);
    }
    __syncthreads();
}

__global__ __launch_bounds__(NTHR, 1) void darts_persistent_kernel(
    const int* __restrict__ X, const float* __restrict__ hidden,
    const float* __restrict__ emb, const float* __restrict__ W0,
    const float* __restrict__ Ws, const float* __restrict__ Wout,
    const float* __restrict__ bout, float* __restrict__ out, int out_size)
{
    __shared__ u64_t red[8 * 32 * 16];   // 32 KB two-stage reduction buffer
    const int cta = blockIdx.x;
    const int tid = threadIdx.x;

    // init: transposed hidden and embT for t=0
    {
        int idx = cta * 512 + tid;
        int k = idx >> 6, row = idx & 63;
        g_hT[idx] = hidden[(size_t)row * Hh + k];
        int tok = __ldg(&X[row]);
        g_embT[idx] = __ldg(&emb[(size_t)tok * Hh + k]);
    }
    grid_sync();

    const size_t WSZ = (size_t)Hh * K2H;
    const int j0 = cta * 8;

    for (int t = 0; t < TSTEPS; t++) {
        // L0: s0 from [emb ; h] @ W0, gate base = h, act tanh
        gemm_tile(W0, g_embT, g_hT, Hh, K2H, g_hT, g_sT[0], j0, 0, red);
        grid_sync();

        // L1: s1 = node0(s0), sigmoid
        gemm_tile(Ws + 0 * WSZ, g_sT[0], g_sT[0], Hh, Hh, g_sT[0], g_sT[1], j0, 2, red);
        grid_sync();

        // L2: s2 = node1(s1) relu, s3 = node2(s1) relu, s4 = node3(s1) identity
        gemm_tile(Ws + 1 * WSZ, g_sT[1], g_sT[1], Hh, Hh, g_sT[1], g_sT[2], j0, 1, red);
        gemm_tile(Ws + 2 * WSZ, g_sT[1], g_sT[1], Hh, Hh, g_sT[1], g_sT[3], j0, 1, red);
        gemm_tile(Ws + 3 * WSZ, g_sT[1], g_sT[1], Hh, Hh, g_sT[1], g_sT[4], j0, 3, red);
        grid_sync();

        // L3: s5 = node4(s2), tanh
        gemm_tile(Ws + 4 * WSZ, g_sT[2], g_sT[2], Hh, Hh, g_sT[2], g_sT[5], j0, 0, red);
        grid_sync();

        // L4: s7 = node6(s3) tanh, s6 = node5(s5) sigmoid, s8 = node7(s5) relu
        gemm_tile(Ws + 6 * WSZ, g_sT[3], g_sT[3], Hh, Hh, g_sT[3], g_sT[7], j0, 0, red);
        gemm_tile(Ws + 5 * WSZ, g_sT[5], g_sT[5], Hh, Hh, g_sT[5], g_sT[6], j0, 2, red);
        gemm_tile(Ws + 7 * WSZ, g_sT[5], g_sT[5], Hh, Hh, g_sT[5], g_sT[8], j0, 1, red);

        // fused combine (own cols; s6/s7/s8 written by this CTA) + embT gather for t+1
        {
            int idx = cta * 512 + tid;
            float s = 0.f;
            #pragma unroll
            for (int n = 1; n <= 8; n++) s += ldcg_f(&g_sT[n][idx]);
            g_hT[idx] = s * 0.125f;
            if (t + 1 < TSTEPS) {
                int k = idx >> 6, row = idx & 63;
                int tok = __ldg(&X[(t + 1) * Bb + row]);
                g_embT[idx] = __ldg(&emb[(size_t)tok * Hh + k]);
            }
        }
        grid_sync();
    }

    // head: a_hat = h @ W_out + b_out; probs = softmax (4-wide, lane-aligned groups)
    if (cta == 0 && tid < 256) {
        int b = tid >> 2, o = tid & 3;
        float acc = 0.f;
        for (int k = 0; k < Hh; k++) acc += ldcg_f(&g_hT[(size_t)k * Bb + b]) * Wout[k * 4 + o];
        acc += bout[o];
        float m = acc;
        m = fmaxf(m, __shfl_xor_sync(0xFFFFFFFFu, m, 1));
        m = fmaxf(m, __shfl_xor_sync(0xFFFFFFFFu, m, 2));
        float e = expf(acc - m);
        float ssum = e;
        ssum += __shfl_xor_sync(0xFFFFFFFFu, ssum, 1);
        ssum += __shfl_xor_sync(0xFFFFFFFFu, ssum, 2);
        out[b * 4 + o] = acc;
        if (out_size >= 512) out[256 + b * 4 + o] = e / ssum;
    }
}

extern "C" void kernel_launch(void* const* d_in, const int* in_sizes, int n_in,
                              void* d_out, int out_size) {
    const int*   X      = (const int*)d_in[0];
    const float* hidden = (const float*)d_in[1];
    const float* emb    = (const float*)d_in[2];
    const float* W0     = (const float*)d_in[3];
    const float* Ws     = (const float*)d_in[4];
    const float* W_out  = (const float*)d_in[5];
    const float* b_out  = (const float*)d_in[6];
    (void)in_sizes; (void)n_in;

    darts_persistent_kernel<<<NCTA, NTHR>>>(X, hidden, emb, W0, Ws, W_out, b_out,
                                            (float*)d_out, out_size);
}

// round 10
// speedup vs baseline: 1.1219x; 1.1219x over previous
#include <cuda_runtime.h>

#define NCTA 128
#define NTHR 512
#define TSTEPS 512
#define Bb 64
#define Hh 1024
#define K2H 2048

typedef unsigned long long u64_t;

// Persistent device state. All transposed: [col][row], row=batch.
__device__ float g_sT[9][Hh * Bb];
__device__ float g_hT[Hh * Bb];
__device__ float g_embT[Hh * Bb];
__device__ unsigned g_count = 0;   // monotonic across barriers AND graph replays
__device__ unsigned g_gen = 0;

union F4U { float4 f; u64_t u[2]; };

// ---- packed f32x2 (Blackwell) ----
__device__ __forceinline__ u64_t pack2(float lo, float hi) {
    u64_t r; asm("mov.b64 %0, {%1, %2};" : "=l"(r) : "f"(lo), "f"(hi)); return r;
}
__device__ __forceinline__ void fma2(u64_t& d, u64_t a, u64_t b) {
    asm("fma.rn.f32x2 %0, %1, %2, %3;" : "=l"(d) : "l"(a), "l"(b), "l"(d));
}
__device__ __forceinline__ u64_t add2(u64_t a, u64_t b) {
    u64_t d; asm("add.rn.f32x2 %0, %1, %2;" : "=l"(d) : "l"(a), "l"(b)); return d;
}
__device__ __forceinline__ float ldcg_f(const float* p) {
    float v; asm volatile("ld.global.cg.f32 %0, [%1];" : "=f"(v) : "l"(p)); return v;
}
__device__ __forceinline__ float4 ldcg_f4(const float* p) {
    float4 v;
    asm volatile("ld.global.cg.v4.f32 {%0,%1,%2,%3}, [%4];"
                 : "=f"(v.x), "=f"(v.y), "=f"(v.z), "=f"(v.w) : "l"(p));
    return v;
}

__device__ __forceinline__ float sigm(float x) { return 1.f / (1.f + expf(-x)); }
__device__ __forceinline__ float actf(int code, float x) {
    switch (code) {
        case 0:  return tanhf(x);
        case 1:  return fmaxf(x, 0.f);
        case 2:  return sigm(x);
        default: return x;
    }
}

// Monotonic-generation grid barrier (proven fastest variant).
__device__ __forceinline__ void grid_sync() {
    __syncthreads();
    if (threadIdx.x == 0) {
        __threadfence();
        unsigned arr = atomicAdd(&g_count, 1u) + 1u;
        unsigned want = (arr + NCTA - 1u) / NCTA;
        if (arr % NCTA == 0u) atomicAdd(&g_gen, 1u);
        while (*((volatile unsigned*)&g_gen) < want) { }
        __threadfence();
    }
    __syncthreads();
}

// One 8-col x 64-row output tile: out = gated(Sin); pre-act = x @ W (W:[K][2048], c|h halves).
// x transposed [k][64]; 16 warps split K. Distance-4 register pipeline: 12 LDGs in
// flight per warp, consumption 4 k behind issue.
__device__ __noinline__ void gemm_tile(
    const float* __restrict__ W, const float* __restrict__ xA,
    const float* __restrict__ xB, int Ka, int K,
    const float* __restrict__ gateT, float* __restrict__ outT,
    int j0, int act, u64_t* red)
{
    const int lane = threadIdx.x & 31;
    const int warp = threadIdx.x >> 5;
    const int ct = lane & 1;           // 2 col-threads: 4 cols each
    const int g  = lane >> 1;          // 16 row-groups: 4 rows each
    const int colbase = j0 + ct * 4;
    const int rowbase = g * 4;
    const int kslice = K >> 4;         // 16-way K split
    const int kbeg = warp * kslice;

    const float* xp = ((kbeg < Ka) ? (xA + (size_t)kbeg * Bb)
                                   : (xB + (size_t)(kbeg - Ka) * Bb)) + rowbase;
    const float* wp = W + (size_t)kbeg * K2H + colbase;

    u64_t acc[4][2][2];                // [row r][colpair cp][half h]
    #pragma unroll
    for (int r = 0; r < 4; r++)
        #pragma unroll
        for (int cp = 0; cp < 2; cp++) { acc[r][cp][0] = 0ull; acc[r][cp][1] = 0ull; }

    // distance-4 pipeline buffers
    float4 xq[4];
    F4U wcq[4], whq[4];
    #pragma unroll
    for (int p = 0; p < 4; p++) {
        xq[p]    = ldcg_f4(xp + (size_t)p * Bb);
        wcq[p].f = __ldg((const float4*)(wp + (size_t)p * K2H));
        whq[p].f = __ldg((const float4*)(wp + (size_t)p * K2H + Hh));
    }

    #pragma unroll 4
    for (int k = 0; k < kslice - 4; k++) {
        const int b = k & 3;
        float4 xv = xq[b];
        F4U wc = wcq[b], wh = whq[b];
        // prefetch k+4 into the freed slot
        xq[b]    = ldcg_f4(xp + (size_t)(k + 4) * Bb);
        wcq[b].f = __ldg((const float4*)(wp + (size_t)(k + 4) * K2H));
        whq[b].f = __ldg((const float4*)(wp + (size_t)(k + 4) * K2H + Hh));

        u64_t xb;
        xb = pack2(xv.x, xv.x);
        fma2(acc[0][0][0], xb, wc.u[0]); fma2(acc[0][1][0], xb, wc.u[1]);
        fma2(acc[0][0][1], xb, wh.u[0]); fma2(acc[0][1][1], xb, wh.u[1]);
        xb = pack2(xv.y, xv.y);
        fma2(acc[1][0][0], xb, wc.u[0]); fma2(acc[1][1][0], xb, wc.u[1]);
        fma2(acc[1][0][1], xb, wh.u[0]); fma2(acc[1][1][1], xb, wh.u[1]);
        xb = pack2(xv.z, xv.z);
        fma2(acc[2][0][0], xb, wc.u[0]); fma2(acc[2][1][0], xb, wc.u[1]);
        fma2(acc[2][0][1], xb, wh.u[0]); fma2(acc[2][1][1], xb, wh.u[1]);
        xb = pack2(xv.w, xv.w);
        fma2(acc[3][0][0], xb, wc.u[0]); fma2(acc[3][1][0], xb, wc.u[1]);
        fma2(acc[3][0][1], xb, wh.u[0]); fma2(acc[3][1][1], xb, wh.u[1]);
    }

    // epilogue: last 4 k from buffers
    #pragma unroll
    for (int p = 0; p < 4; p++) {
        const int b = (kslice - 4 + p) & 3;
        float4 xv = xq[b];
        F4U wc = wcq[b], wh = whq[b];
        u64_t xb;
        xb = pack2(xv.x, xv.x);
        fma2(acc[0][0][0], xb, wc.u[0]); fma2(acc[0][1][0], xb, wc.u[1]);
        fma2(acc[0][0][1], xb, wh.u[0]); fma2(acc[0][1][1], xb, wh.u[1]);
        xb = pack2(xv.y, xv.y);
        fma2(acc[1][0][0], xb, wc.u[0]); fma2(acc[1][1][0], xb, wc.u[1]);
        fma2(acc[1][0][1], xb, wh.u[0]); fma2(acc[1][1][1], xb, wh.u[1]);
        xb = pack2(xv.z, xv.z);
        fma2(acc[2][0][0], xb, wc.u[0]); fma2(acc[2][1][0], xb, wc.u[1]);
        fma2(acc[2][0][1], xb, wh.u[0]); fma2(acc[2][1][1], xb, wh.u[1]);
        xb = pack2(xv.w, xv.w);
        fma2(acc[3][0][0], xb, wc.u[0]); fma2(acc[3][1][0], xb, wc.u[1]);
        fma2(acc[3][0][1], xb, wh.u[0]); fma2(acc[3][1][1], xb, wh.u[1]);
    }

    // Stage 1: warps 8..15 store partials into slot (warp-8).
    if (warp >= 8) {
        u64_t* my = red + ((size_t)((warp - 8) * 32 + lane)) * 16;
        #pragma unroll
        for (int r = 0; r < 4; r++)
            #pragma unroll
            for (int cp = 0; cp < 2; cp++) {
                my[(r * 4 + cp * 2) + 0] = acc[r][cp][0];
                my[(r * 4 + cp * 2) + 1] = acc[r][cp][1];
            }
    }
    __syncthreads();

    // Stage 2: warps 0..7 add partner partials into slot warp.
    if (warp < 8) {
        u64_t* my = red + ((size_t)(warp * 32 + lane)) * 16;
        #pragma unroll
        for (int r = 0; r < 4; r++)
            #pragma unroll
            for (int cp = 0; cp < 2; cp++) {
                int i0 = r * 4 + cp * 2;
                my[i0 + 0] = add2(my[i0 + 0], acc[r][cp][0]);
                my[i0 + 1] = add2(my[i0 + 1], acc[r][cp][1]);
            }
    }
    __syncthreads();

    // Stage 3: 512 threads finalize 512 outputs (8 cols x 64 rows).
    {
        const int t   = threadIdx.x;
        const int c8  = t & 7;
        const int row = t >> 3;
        const int sct = c8 >> 2;
        const int cp  = (c8 >> 1) & 1;
        const int par = c8 & 1;
        const int sg  = row >> 2;
        const int r   = row & 3;
        const int slane = sg * 2 + sct;
        const float* redf = (const float*)red;
        const int fbase = slane * 32 + (r * 4 + cp * 2) * 2 + par;

        float sc = 0.f, sh = 0.f;
        #pragma unroll
        for (int s = 0; s < 8; s++) {
            const float* rp = redf + (size_t)s * 32 * 32 + fbase;
            sc += rp[0];
            sh += rp[2];
        }
        const int col = j0 + c8;
        const size_t o = (size_t)col * Bb + row;
        float sp = ldcg_f(gateT + o);
        float cv = sigm(sc);
        float hv = actf(act, sh);
        outT[o] = sp + cv * (hv - sp);
    }
    __syncthreads();
}

__global__ __launch_bounds__(NTHR, 1) void darts_persistent_kernel(
    const int* __restrict__ X, const float* __restrict__ hidden,
    const float* __restrict__ emb, const float* __restrict__ W0,
    const float* __restrict__ Ws, const float* __restrict__ Wout,
    const float* __restrict__ bout, float* __restrict__ out, int out_size)
{
    __shared__ u64_t red[8 * 32 * 16];   // 32 KB two-stage reduction buffer
    const int cta = blockIdx.x;
    const int tid = threadIdx.x;

    // init: transposed hidden and embT for t=0
    {
        int idx = cta * 512 + tid;
        int k = idx >> 6, row = idx & 63;
        g_hT[idx] = hidden[(size_t)row * Hh + k];
        int tok = __ldg(&X[row]);
        g_embT[idx] = __ldg(&emb[(size_t)tok * Hh + k]);
    }
    grid_sync();

    const size_t WSZ = (size_t)Hh * K2H;
    const int j0 = cta * 8;

    for (int t = 0; t < TSTEPS; t++) {
        // L0: s0 from [emb ; h] @ W0, gate base = h, act tanh
        gemm_tile(W0, g_embT, g_hT, Hh, K2H, g_hT, g_sT[0], j0, 0, red);
        grid_sync();

        // L1: s1 = node0(s0), sigmoid
        gemm_tile(Ws + 0 * WSZ, g_sT[0], g_sT[0], Hh, Hh, g_sT[0], g_sT[1], j0, 2, red);
        grid_sync();

        // L2: s2 = node1(s1) relu, s3 = node2(s1) relu, s4 = node3(s1) identity
        gemm_tile(Ws + 1 * WSZ, g_sT[1], g_sT[1], Hh, Hh, g_sT[1], g_sT[2], j0, 1, red);
        gemm_tile(Ws + 2 * WSZ, g_sT[1], g_sT[1], Hh, Hh, g_sT[1], g_sT[3], j0, 1, red);
        gemm_tile(Ws + 3 * WSZ, g_sT[1], g_sT[1], Hh, Hh, g_sT[1], g_sT[4], j0, 3, red);
        grid_sync();

        // L3: s5 = node4(s2), tanh
        gemm_tile(Ws + 4 * WSZ, g_sT[2], g_sT[2], Hh, Hh, g_sT[2], g_sT[5], j0, 0, red);
        grid_sync();

        // L4: s7 = node6(s3) tanh, s6 = node5(s5) sigmoid, s8 = node7(s5) relu
        gemm_tile(Ws + 6 * WSZ, g_sT[3], g_sT[3], Hh, Hh, g_sT[3], g_sT[7], j0, 0, red);
        gemm_tile(Ws + 5 * WSZ, g_sT[5], g_sT[5], Hh, Hh, g_sT[5], g_sT[6], j0, 2, red);
        gemm_tile(Ws + 7 * WSZ, g_sT[5], g_sT[5], Hh, Hh, g_sT[5], g_sT[8], j0, 1, red);

        // fused combine (own cols; s6/s7/s8 written by this CTA) + embT gather for t+1
        {
            int idx = cta * 512 + tid;
            float s = 0.f;
            #pragma unroll
            for (int n = 1; n <= 8; n++) s += ldcg_f(&g_sT[n][idx]);
            g_hT[idx] = s * 0.125f;
            if (t + 1 < TSTEPS) {
                int k = idx >> 6, row = idx & 63;
                int tok = __ldg(&X[(t + 1) * Bb + row]);
                g_embT[idx] = __ldg(&emb[(size_t)tok * Hh + k]);
            }
        }
        grid_sync();
    }

    // head: a_hat = h @ W_out + b_out; probs = softmax (4-wide, lane-aligned groups)
    if (cta == 0 && tid < 256) {
        int b = tid >> 2, o = tid & 3;
        float acc = 0.f;
        for (int k = 0; k < Hh; k++) acc += ldcg_f(&g_hT[(size_t)k * Bb + b]) * Wout[k * 4 + o];
        acc += bout[o];
        float m = acc;
        m = fmaxf(m, __shfl_xor_sync(0xFFFFFFFFu, m, 1));
        m = fmaxf(m, __shfl_xor_sync(0xFFFFFFFFu, m, 2));
        float e = expf(acc - m);
        float ssum = e;
        ssum += __shfl_xor_sync(0xFFFFFFFFu, ssum, 1);
        ssum += __shfl_xor_sync(0xFFFFFFFFu, ssum, 2);
        out[b * 4 + o] = acc;
        if (out_size >= 512) out[256 + b * 4 + o] = e / ssum;
    }
}

extern "C" void kernel_launch(void* const* d_in, const int* in_sizes, int n_in,
                              void* d_out, int out_size) {
    const int*   X      = (const int*)d_in[0];
    const float* hidden = (const float*)d_in[1];
    const float* emb    = (const float*)d_in[2];
    const float* W0     = (const float*)d_in[3];
    const float* Ws     = (const float*)d_in[4];
    const float* W_out  = (const float*)d_in[5];
    const float* b_out  = (const float*)d_in[6];
    (void)in_sizes; (void)n_in;

    darts_persistent_kernel<<<NCTA, NTHR>>>(X, hidden, emb, W0, Ws, W_out, b_out,
                                            (float*)d_out, out_size);
}

// round 11
// speedup vs baseline: 4.0362x; 3.5976x over previous
#include <cuda_runtime.h>
#include <cuda_bf16.h>

#define NCTA 128
#define NTHR 512
#define TSTEPS 512

typedef unsigned long long u64;
typedef unsigned int u32;

// ---------------- persistent device state ----------------
__device__ float g_hT[1024 * 64];                       // fp32 h, [col][row] for head
__device__ __align__(16) uint4 g_Phi[7][8192];          // swizzled A planes (bf16-hi)
__device__ __align__(16) uint4 g_Plo[7][8192];          // swizzled A planes (bf16-lo)
// plane ids: 0=emb 1=s0 2=s1 3=s2 4=s3 5=s5 6=h
__device__ u64 g_Whi[5242880];                          // swizzled B fragments, bf16-hi (40MB)
__device__ u64 g_Wlo[5242880];                          // bf16-lo (40MB)
__device__ unsigned g_count = 0, g_gen = 0;             // monotonic grid barrier

#define WOFF(i) (1048576u + (u32)(i) * 524288u)         // u64 offset of node-i weights

// ---------------- helpers ----------------
__device__ __forceinline__ float sigm(float x) { return 1.f / (1.f + expf(-x)); }
__device__ __forceinline__ float actf(int code, float x) {
    switch (code) {
        case 0:  return tanhf(x);
        case 1:  return fmaxf(x, 0.f);
        case 2:  return sigm(x);
        default: return x;
    }
}
__device__ __forceinline__ float ldcg_f(const float* p) {
    float v; asm volatile("ld.global.cg.f32 %0, [%1];" : "=f"(v) : "l"(p)); return v;
}
__device__ __forceinline__ void cp_async16(void* smem_dst, const void* gsrc) {
    unsigned s = (unsigned)__cvta_generic_to_shared(smem_dst);
    asm volatile("cp.async.cg.shared.global [%0], [%1], 16;" :: "r"(s), "l"(gsrc));
}

__device__ __forceinline__ void mma_bf16(float* d, u32 a0, u32 a1, u32 a2, u32 a3,
                                         u32 b0, u32 b1) {
    asm("mma.sync.aligned.m16n8k16.row.col.f32.bf16.bf16.f32 "
        "{%0,%1,%2,%3},{%4,%5,%6,%7},{%8,%9},{%0,%1,%2,%3};"
        : "+f"(d[0]), "+f"(d[1]), "+f"(d[2]), "+f"(d[3])
        : "r"(a0), "r"(a1), "r"(a2), "r"(a3), "r"(b0), "r"(b1));
}

__device__ __forceinline__ u64 pack4(__nv_bfloat16 a, __nv_bfloat16 b,
                                     __nv_bfloat16 c, __nv_bfloat16 d) {
    return (u64)__bfloat16_as_ushort(a) | ((u64)__bfloat16_as_ushort(b) << 16)
         | ((u64)__bfloat16_as_ushort(c) << 32) | ((u64)__bfloat16_as_ushort(d) << 48);
}
__device__ __forceinline__ void packhl(float v0, float v1, float v2, float v3,
                                       u64& hi, u64& lo) {
    __nv_bfloat16 h0 = __float2bfloat16_rn(v0), h1 = __float2bfloat16_rn(v1),
                  h2 = __float2bfloat16_rn(v2), h3 = __float2bfloat16_rn(v3);
    __nv_bfloat16 l0 = __float2bfloat16_rn(v0 - __bfloat162float(h0)),
                  l1 = __float2bfloat16_rn(v1 - __bfloat162float(h1)),
                  l2 = __float2bfloat16_rn(v2 - __bfloat162float(h2)),
                  l3 = __float2bfloat16_rn(v3 - __bfloat162float(h3));
    hi = pack4(h0, h1, h2, h3);
    lo = pack4(l0, l1, l2, l3);
}

__device__ __forceinline__ void grid_sync() {
    __syncthreads();
    if (threadIdx.x == 0) {
        __threadfence();
        unsigned arr = atomicAdd(&g_count, 1u) + 1u;
        unsigned want = (arr + NCTA - 1u) / NCTA;
        if (arr % NCTA == 0u) atomicAdd(&g_gen, 1u);
        while (*((volatile unsigned*)&g_gen) < want) { }
        __threadfence();
    }
    __syncthreads();
}

// Write this CTA's 8 state cols (scratch[col*65+row]) into an A plane, fragment-swizzled.
// tt in [0,128). Fragment u64 = {A[g][k0],A[g][k1],A[g+8][k0],A[g+8][k1]} (a0,a1) for even
// cta, (a2,a3) for odd cta; uint4 index = (kt*4+mt)*32+lane with kt = cta>>1.
__device__ __forceinline__ void swz_scr(const float* sc, u64* dh, u64* dl, int cta, int tt) {
    int mt = tt >> 5, lane = tt & 31, g = lane >> 2, c = lane & 3;
    int jA = 2 * c, mA = mt * 16 + g, mB = mA + 8;
    float v00 = sc[jA * 65 + mA], v01 = sc[(jA + 1) * 65 + mA];
    float v10 = sc[jA * 65 + mB], v11 = sc[(jA + 1) * 65 + mB];
    u64 hi, lo; packhl(v00, v01, v10, v11, hi, lo);
    int idx = ((((cta >> 1) * 4 + mt) * 32 + lane) << 1) + (cta & 1);
    dh[idx] = hi; dl[idx] = lo;
}

// Gather embedding rows directly into the swizzled emb plane. tt in [0,128).
__device__ __forceinline__ void swz_emb(const float* __restrict__ emb, const int* stok,
                                        u64* dh, u64* dl, int cta, int j0, int tt) {
    int mt = tt >> 5, lane = tt & 31, g = lane >> 2, c = lane & 3;
    int jA = j0 + 2 * c, mA = mt * 16 + g, mB = mA + 8;
    size_t tA = (size_t)stok[mA] * 1024, tB = (size_t)stok[mB] * 1024;
    float v00 = __ldg(emb + tA + jA), v01 = __ldg(emb + tA + jA + 1);
    float v10 = __ldg(emb + tB + jA), v11 = __ldg(emb + tB + jA + 1);
    u64 hi, lo; packhl(v00, v01, v10, v11, hi, lo);
    int idx = ((((cta >> 1) * 4 + mt) * 32 + lane) << 1) + (cta & 1);
    dh[idx] = hi; dl[idx] = lo;
}

struct ND {
    const u64* wh; const u64* wl;   // swizzled weight base (node offset applied)
    int act;                        // 0 tanh 1 relu 2 sigmoid 3 id
    float sp;                       // per-thread gate base (pred state element)
    u64* szh; u64* szl;             // swizzled output plane (null = skip)
};

// One level: NN nodes sharing the same A operand. Each CTA computes its 8 state
// cols x 64 rows for every node. 16 warps = 4 mt x 2 nt x 2 kh.
template<int NN>
__device__ __forceinline__ void gemm_level(
    const uint4* Ph0, const uint4* Pl0, const uint4* Ph1, const uint4* Pl1,
    int nchunks, int switch_chunk, int nkt,
    ND* nd, float* outv,
    uint4* xsh, uint4* xsl, float* bufA, float* bufB, float* scratch, int cta)
{
    const int tid = threadIdx.x;
    const int lane = tid & 31, warp = tid >> 5;
    const int mt = warp & 3, nt = (warp >> 2) & 1, kh = warp >> 3;
    const int n8c = cta + (nt << 7);
    const int bbase = n8c * nkt * 32 + lane;

    float acc[NN][4];
    #pragma unroll
    for (int n = 0; n < NN; n++)
        #pragma unroll
        for (int i = 0; i < 4; i++) acc[n][i] = 0.f;

    // stage chunk 0
    cp_async16(xsh + tid, Ph0 + tid);
    cp_async16(xsl + tid, Pl0 + tid);
    asm volatile("cp.async.commit_group;");

    for (int c = 0; c < nchunks; c++) {
        const int cur = c & 1;
        if (c + 1 < nchunks) {
            int cn = c + 1;
            const uint4* gh; const uint4* gl;
            if (cn < switch_chunk) { gh = Ph0 + cn * 512; gl = Pl0 + cn * 512; }
            else { gh = Ph1 + (cn - switch_chunk) * 512; gl = Pl1 + (cn - switch_chunk) * 512; }
            int slot = (cur ^ 1) * 512;
            cp_async16(xsh + slot + tid, gh + tid);
            cp_async16(xsl + slot + tid, gl + tid);
            asm volatile("cp.async.commit_group;");
            asm volatile("cp.async.wait_group 1;");
        } else {
            asm volatile("cp.async.wait_group 0;");
        }
        __syncthreads();

        #pragma unroll
        for (int kf2 = 0; kf2 < 2; kf2++) {
            const int kf = kh * 2 + kf2;
            uint4 ah = xsh[cur * 512 + (kf * 4 + mt) * 32 + lane];
            uint4 al = xsl[cur * 512 + (kf * 4 + mt) * 32 + lane];
            const int koff = (c * 4 + kf) * 32;
            #pragma unroll
            for (int n = 0; n < NN; n++) {
                u64 bh = __ldg(nd[n].wh + bbase + koff);
                u64 bl = __ldg(nd[n].wl + bbase + koff);
                u32 bh0 = (u32)bh, bh1 = (u32)(bh >> 32);
                u32 bl0 = (u32)bl, bl1 = (u32)(bl >> 32);
                mma_bf16(acc[n], ah.x, ah.y, ah.z, ah.w, bh0, bh1);
                mma_bf16(acc[n], ah.x, ah.y, ah.z, ah.w, bl0, bl1);
                mma_bf16(acc[n], al.x, al.y, al.z, al.w, bh0, bh1);
            }
        }
        __syncthreads();
    }

    // per-node cross-kh reduction + epilogue
    const int c8 = tid & 7, row = tid >> 3;
    const int nl = nt * 8 + 2 * (lane & 3);
    const int m  = mt * 16 + (lane >> 2);
    float* mybuf = kh ? bufB : bufA;

    #pragma unroll
    for (int n = 0; n < NN; n++) {
        mybuf[nl * 68 + m]           = acc[n][0];
        mybuf[(nl + 1) * 68 + m]     = acc[n][1];
        mybuf[nl * 68 + m + 8]       = acc[n][2];
        mybuf[(nl + 1) * 68 + m + 8] = acc[n][3];
        __syncthreads();
        float cpre = bufA[c8 * 68 + row] + bufB[c8 * 68 + row];
        float hpre = bufA[(8 + c8) * 68 + row] + bufB[(8 + c8) * 68 + row];
        float cv = sigm(cpre);
        float hv = actf(nd[n].act, hpre);
        float sp = nd[n].sp;
        float val = sp + cv * (hv - sp);
        outv[n] = val;
        if (nd[n].szh) {
            scratch[c8 * 65 + row] = val;
            __syncthreads();
            if (tid < 128) swz_scr(scratch, nd[n].szh, nd[n].szl, cta, tid);
        }
        __syncthreads();
    }
}

// ---------------- the persistent kernel ----------------
__global__ __launch_bounds__(NTHR, 1) void darts_mma_kernel(
    const int* __restrict__ X, const float* __restrict__ hidden,
    const float* __restrict__ emb, const float* __restrict__ W0,
    const float* __restrict__ Ws, const float* __restrict__ Wout,
    const float* __restrict__ bout, float* __restrict__ out, int out_size)
{
    __shared__ uint4 xsh[2 * 512];        // 16 KB A-hi double buffer
    __shared__ uint4 xsl[2 * 512];        // 16 KB A-lo double buffer
    __shared__ float bufA[16 * 68], bufB[16 * 68];
    __shared__ float scratch[8 * 65];
    __shared__ int stok[64];

    const int cta = blockIdx.x;
    const int tid = threadIdx.x;
    const int j0 = cta * 8;
    const int c8 = tid & 7, row = tid >> 3;

    // Phase 1: weights fp32 -> swizzled bf16 hi/lo fragment quads (every launch).
    for (u32 q = (u32)(cta * NTHR + tid); q < 5242880u; q += (u32)(NCTA * NTHR)) {
        const float* src; u32 rem, ktmask, n8sh;
        if (q < 1048576u) { src = W0; rem = q; ktmask = 127u; n8sh = 7u; }
        else {
            u32 r = q - 1048576u;
            src = Ws + (size_t)(r >> 19) * 2097152u;
            rem = r & 524287u; ktmask = 63u; n8sh = 6u;
        }
        u32 lane = rem & 31u, t2 = rem >> 5;
        u32 kt = t2 & ktmask, n8 = t2 >> n8sh;
        u32 g = lane >> 2, c = lane & 3;
        u32 k0 = kt * 16 + 2 * c;
        u32 n = n8 * 8 + g;
        float v0 = __ldg(src + (size_t)k0 * 2048 + n);
        float v1 = __ldg(src + (size_t)(k0 + 1) * 2048 + n);
        float v2 = __ldg(src + (size_t)(k0 + 8) * 2048 + n);
        float v3 = __ldg(src + (size_t)(k0 + 9) * 2048 + n);
        u64 hi, lo; packhl(v0, v1, v2, v3, hi, lo);
        g_Whi[q] = hi; g_Wlo[q] = lo;
    }

    // Phase 2: init h (fp32 + plane) and emb plane for t=0.
    float hreg = __ldg(&hidden[row * 1024 + j0 + c8]);
    g_hT[(j0 + c8) * 64 + row] = hreg;
    scratch[c8 * 65 + row] = hreg;
    if (tid < 64) stok[tid] = __ldg(&X[tid]);
    __syncthreads();
    if (tid < 128) swz_scr(scratch, (u64*)g_Phi[6], (u64*)g_Plo[6], cta, tid);
    else if (tid < 256) swz_emb(emb, stok, (u64*)g_Phi[0], (u64*)g_Plo[0], cta, j0, tid - 128);
    grid_sync();

    float sv1, sv2, sv3, sv5;
    float o[3];
    ND nd[3];

    for (int t = 0; t < TSTEPS; t++) {
        // L0: s0 = gate([emb;h] @ W0), base h, act tanh. K=2048 (emb plane then h plane).
        nd[0] = { g_Whi, g_Wlo, 0, hreg, (u64*)g_Phi[1], (u64*)g_Plo[1] };
        gemm_level<1>(g_Phi[0], g_Plo[0], g_Phi[6], g_Plo[6], 32, 16, 128,
                      nd, o, xsh, xsl, bufA, bufB, scratch, cta);
        float sv0 = o[0];
        grid_sync();

        // L1: s1 = node0(s0), sigmoid
        nd[0] = { g_Whi + WOFF(0), g_Wlo + WOFF(0), 2, sv0, (u64*)g_Phi[2], (u64*)g_Plo[2] };
        gemm_level<1>(g_Phi[1], g_Plo[1], g_Phi[1], g_Plo[1], 16, 16, 64,
                      nd, o, xsh, xsl, bufA, bufB, scratch, cta);
        sv1 = o[0];
        grid_sync();

        // L2: s2=node1(s1) relu, s3=node2(s1) relu, s4=node3(s1) id — share A=s1
        nd[0] = { g_Whi + WOFF(1), g_Wlo + WOFF(1), 1, sv1, (u64*)g_Phi[3], (u64*)g_Plo[3] };
        nd[1] = { g_Whi + WOFF(2), g_Wlo + WOFF(2), 1, sv1, (u64*)g_Phi[4], (u64*)g_Plo[4] };
        nd[2] = { g_Whi + WOFF(3), g_Wlo + WOFF(3), 3, sv1, (u64*)0, (u64*)0 };
        gemm_level<3>(g_Phi[2], g_Plo[2], g_Phi[2], g_Plo[2], 16, 16, 64,
                      nd, o, xsh, xsl, bufA, bufB, scratch, cta);
        sv2 = o[0]; sv3 = o[1];
        float sv4 = o[2];
        grid_sync();

        // L3: s5 = node4(s2), tanh
        nd[0] = { g_Whi + WOFF(4), g_Wlo + WOFF(4), 0, sv2, (u64*)g_Phi[5], (u64*)g_Plo[5] };
        gemm_level<1>(g_Phi[3], g_Plo[3], g_Phi[3], g_Plo[3], 16, 16, 64,
                      nd, o, xsh, xsl, bufA, bufB, scratch, cta);
        sv5 = o[0];
        grid_sync();

        // L4a: s7 = node6(s3), tanh (A = s3 plane; already synced)
        nd[0] = { g_Whi + WOFF(6), g_Wlo + WOFF(6), 0, sv3, (u64*)0, (u64*)0 };
        gemm_level<1>(g_Phi[4], g_Plo[4], g_Phi[4], g_Plo[4], 16, 16, 64,
                      nd, o, xsh, xsl, bufA, bufB, scratch, cta);
        float sv7 = o[0];

        // L4b: s6 = node5(s5) sigmoid, s8 = node7(s5) relu (A = s5 plane)
        nd[0] = { g_Whi + WOFF(5), g_Wlo + WOFF(5), 2, sv5, (u64*)0, (u64*)0 };
        nd[1] = { g_Whi + WOFF(7), g_Wlo + WOFF(7), 1, sv5, (u64*)0, (u64*)0 };
        gemm_level<2>(g_Phi[5], g_Plo[5], g_Phi[5], g_Plo[5], 16, 16, 64,
                      nd, o, xsh, xsl, bufA, bufB, scratch, cta);
        float sv6 = o[0], sv8 = o[1];

        // combine: h = mean(s1..s8) in registers; write fp32 h + h plane + next emb plane
        hreg = 0.125f * (sv1 + sv2 + sv3 + sv4 + sv5 + sv6 + sv7 + sv8);
        g_hT[(j0 + c8) * 64 + row] = hreg;
        scratch[c8 * 65 + row] = hreg;
        if (tid < 64 && t + 1 < TSTEPS) stok[tid] = __ldg(&X[(t + 1) * 64 + tid]);
        __syncthreads();
        if (tid < 128) swz_scr(scratch, (u64*)g_Phi[6], (u64*)g_Plo[6], cta, tid);
        else if (tid < 256 && t + 1 < TSTEPS)
            swz_emb(emb, stok, (u64*)g_Phi[0], (u64*)g_Plo[0], cta, j0, tid - 128);
        grid_sync();
    }

    // head: a_hat = h @ W_out + b_out; probs = softmax over 4 (lane-aligned groups)
    if (cta == 0 && tid < 256) {
        int b = tid >> 2, oo = tid & 3;
        float acc = 0.f;
        for (int k = 0; k < 1024; k++)
            acc += ldcg_f(&g_hT[k * 64 + b]) * __ldg(&Wout[k * 4 + oo]);
        acc += __ldg(&bout[oo]);
        float mx = acc;
        mx = fmaxf(mx, __shfl_xor_sync(0xFFFFFFFFu, mx, 1));
        mx = fmaxf(mx, __shfl_xor_sync(0xFFFFFFFFu, mx, 2));
        float e = expf(acc - mx);
        float ssum = e;
        ssum += __shfl_xor_sync(0xFFFFFFFFu, ssum, 1);
        ssum += __shfl_xor_sync(0xFFFFFFFFu, ssum, 2);
        out[b * 4 + oo] = acc;
        if (out_size >= 512) out[256 + b * 4 + oo] = e / ssum;
    }
}

extern "C" void kernel_launch(void* const* d_in, const int* in_sizes, int n_in,
                              void* d_out, int out_size) {
    const int*   X      = (const int*)d_in[0];
    const float* hidden = (const float*)d_in[1];
    const float* emb    = (const float*)d_in[2];
    const float* W0     = (const float*)d_in[3];
    const float* Ws     = (const float*)d_in[4];
    const float* W_out  = (const float*)d_in[5];
    const float* b_out  = (const float*)d_in[6];
    (void)in_sizes; (void)n_in;

    darts_mma_kernel<<<NCTA, NTHR>>>(X, hidden, emb, W0, Ws, W_out, b_out,
                                     (float*)d_out, out_size);
}